// round 13
// baseline (speedup 1.0000x reference)
#include <cuda_runtime.h>
#include <cstdint>
#include <cfloat>

#define BATCH 64
#define UNUM  1024
#define ENUM  1024
#define UFD   512
#define EFD   256

__device__ float g_scale;
__device__ float g_part[32];
__device__ int   g_ne[BATCH];
__device__ uint2 g_ebf2[(size_t)BATCH * 16 * 128 * 32];  // efeat B-frags fp16 hi
__device__ uint4 g_ubf2[(size_t)4096 * 32 * 32];         // ufeat A-frags fp16 hi
__device__ uint2 g_vbf2b[(size_t)32 * 32 * 32];          // v B-frags fp16 hi
__device__ uint4 g_pbf[(size_t)4096 * 512];              // proj A-frags fp16 hi

// ---------------------------------------------------------------------------
// helpers
// ---------------------------------------------------------------------------
__device__ __forceinline__ uint32_t packh(float x0, float x1) {
    uint32_t r;   // {hi16: fp16(x1), lo16: fp16(x0)}
    asm("cvt.rn.f16x2.f32 %0, %1, %2;" : "=r"(r) : "f"(x1), "f"(x0));
    return r;
}
__device__ __forceinline__ void mma_f16(float* d, const uint32_t* a, const uint32_t* b) {
    asm volatile(
        "mma.sync.aligned.m16n8k16.row.col.f32.f16.f16.f32 "
        "{%0,%1,%2,%3}, {%4,%5,%6,%7}, {%8,%9}, {%0,%1,%2,%3};"
        : "+f"(d[0]), "+f"(d[1]), "+f"(d[2]), "+f"(d[3])
        : "r"(a[0]), "r"(a[1]), "r"(a[2]), "r"(a[3]), "r"(b[0]), "r"(b[1]));
}
__device__ __forceinline__ uint32_t smem_u32(const void* p) {
    uint32_t a;
    asm("{ .reg .u64 t; cvta.to.shared.u64 t, %1; cvt.u32.u64 %0, t; }" : "=r"(a) : "l"(p));
    return a;
}
#define CP16(dst, src) \
    asm volatile("cp.async.cg.shared.global [%0], [%1], 16;" :: "r"(dst), "l"(src) : "memory")
#define CP_COMMIT() asm volatile("cp.async.commit_group;" ::: "memory")
#define CP_WAIT2()  asm volatile("cp.async.wait_group 2;" ::: "memory")
#define CP_WAIT1()  asm volatile("cp.async.wait_group 1;" ::: "memory")
#define CP_WAIT0()  asm volatile("cp.async.wait_group 0;" ::: "memory")

// ---------------------------------------------------------------------------
// prep_partial: ||v||^2 partials
// ---------------------------------------------------------------------------
__global__ __launch_bounds__(1024) void prep_partial(const float* __restrict__ v) {
    __shared__ float wsum[32];
    int tid = threadIdx.x, b = blockIdx.x;
    float s = 0.f;
    #pragma unroll
    for (int i = 0; i < 4; i++) {
        float x = v[b * 4096 + i * 1024 + tid];
        s += x * x;
    }
    #pragma unroll
    for (int o = 16; o; o >>= 1) s += __shfl_xor_sync(0xffffffffu, s, o);
    if ((tid & 31) == 0) wsum[tid >> 5] = s;
    __syncthreads();
    if (tid == 0) {
        float tot = 0.f;
        #pragma unroll
        for (int w = 0; w < 32; w++) tot += wsum[w];
        g_part[b] = tot;
    }
}

// ---------------------------------------------------------------------------
// vconv_full: v -> B-frags [c(32)][n8(32)][lane] (fp16 hi)
// ---------------------------------------------------------------------------
__global__ __launch_bounds__(256) void vconv_full(const float* __restrict__ v) {
    uint32_t gid = blockIdx.x * 256 + threadIdx.x;   // 32768
    int lane = gid & 31;
    int n8   = (gid >> 5) & 31;
    int c    = gid >> 10;
    int n    = n8 * 8 + (lane >> 2);
    int k0   = c * 16 + (lane & 3) * 2;
    const float* src = v + (size_t)n * UFD;
    float2 f0 = *(const float2*)(src + k0);
    float2 f1 = *(const float2*)(src + k0 + 8);
    uint2 o;
    o.x = packh(f0.x, f0.y);
    o.y = packh(f1.x, f1.y);
    g_vbf2b[(size_t)(c * 32 + n8) * 32 + lane] = o;
}

// ---------------------------------------------------------------------------
// conv_all: finalize + uconv(hi) + econv(hi), one launch.
// ---------------------------------------------------------------------------
__global__ __launch_bounds__(256) void conv_all(const float* __restrict__ uf,
                                                const float* __restrict__ ef,
                                                const float* __restrict__ g,
                                                const int* __restrict__ ne32) {
    const uint32_t b = blockIdx.x;
    const int t = threadIdx.x;
    if (b == 0 && t == 0) {
        float tot = 0.f;
        #pragma unroll
        for (int i = 0; i < 32; i++) tot += g_part[i];
        g_scale = g[0] / sqrtf(tot);
        bool is64 = true;
        for (int i = 0; i < 32; i++)
            if (ne32[2 * i + 1] != 0) { is64 = false; break; }
        for (int i = 0; i < BATCH; i++) g_ne[i] = is64 ? ne32[2 * i] : ne32[i];
    }

    if (b < 16384) {                    // ---- uconv (hi only) ----
        uint32_t gid = b * 256 + t;
        int lane = gid & 31;
        int c    = (gid >> 5) & 31;
        int m16  = gid >> 10;
        int r    = m16 * 16 + (lane >> 2);
        int k0   = c * 16 + (lane & 3) * 2;
        const float* s0 = uf + (size_t)r * UFD;
        const float* s1 = uf + (size_t)(r + 8) * UFD;
        float2 a0 = *(const float2*)(s0 + k0);
        float2 a1 = *(const float2*)(s1 + k0);
        float2 a2 = *(const float2*)(s0 + k0 + 8);
        float2 a3 = *(const float2*)(s1 + k0 + 8);
        uint4 hi;
        hi.x = packh(a0.x, a0.y); hi.y = packh(a1.x, a1.y);
        hi.z = packh(a2.x, a2.y); hi.w = packh(a3.x, a3.y);
        g_ubf2[gid] = hi;
    } else {                            // ---- econv (hi only) ----
        uint32_t gid = (b - 16384) * 256 + t;
        int lane = gid & 31;
        int n8   = (gid >> 5) & 127;
        int c    = (gid >> 12) & 15;
        int z    = gid >> 16;
        int n    = n8 * 8 + (lane >> 2);
        int k0   = c * 16 + (lane & 3) * 2;
        const float* src = ef + ((size_t)z * ENUM + n) * EFD;
        float2 f0 = *(const float2*)(src + k0);
        float2 f1 = *(const float2*)(src + k0 + 8);
        uint2 o;
        o.x = packh(f0.x, f0.y);
        o.y = packh(f1.x, f1.y);
        g_ebf2[gid] = o;
    }
}

// ---------------------------------------------------------------------------
// proj GEMM: pure fp16 (1 MMA). relu(g_scale*(ufeat@v^T)+bias) -> g_pbf.
// Tile 128x128, 256 thr (2m x 4n warps), 3-stage cp.async. (unchanged)
// ---------------------------------------------------------------------------
#define PSMEM_BYTES (3 * 512 * 16)   // 24 KB

__global__ __launch_bounds__(256, 2) void proj_gemm(const float* __restrict__ bias) {
    extern __shared__ uint4 su[];
    const uint32_t sbase = smem_u32(su);
    const int t = threadIdx.x;
    const int warp = t >> 5, lane = t & 31;
    const int warpM = warp >> 2, warpN = warp & 3;
    const int n0 = blockIdx.x * 128;
    const int m16base = blockIdx.y * 8;
    const int n8base = blockIdx.x * 16;

    float acc[4][4][4];
    #pragma unroll
    for (int i = 0; i < 4; i++)
        #pragma unroll
        for (int j = 0; j < 4; j++)
            #pragma unroll
            for (int r = 0; r < 4; r++) acc[i][j][r] = 0.f;

    constexpr int NCH = UFD / 16;   // 32

    auto issue = [&](int c) {
        const int s = ((unsigned)c) % 3;
        const uint32_t stb = sbase + s * 8192;
        {   // A: 256 uint4
            int m16l = t >> 5, ln = t & 31;
            const uint4* src = g_ubf2 + (size_t)((m16base + m16l) * 32 + c) * 32 + ln;
            CP16(stb + t * 16, src);
        }
        {   // B: 256 uint4
            const uint4* src = (const uint4*)(g_vbf2b + (size_t)(c * 32 + n8base) * 32) + t;
            CP16(stb + (256 + t) * 16, src);
        }
        CP_COMMIT();
    };

    issue(0);
    issue(1);
    #pragma unroll 1
    for (int c = 0; c < NCH; c++) {
        if (c == NCH - 1) CP_WAIT0(); else CP_WAIT1();
        __syncthreads();
        if (c + 2 < NCH) issue(c + 2);

        const uint4* st = su + ((unsigned)c % 3) * 512;
        const uint2* sB2 = (const uint2*)(st + 256);
        uint4 ah[4];
        uint2 bb[4];
        #pragma unroll
        for (int mt = 0; mt < 4; mt++)
            ah[mt] = st[(warpM * 4 + mt) * 32 + lane];
        #pragma unroll
        for (int nt = 0; nt < 4; nt++)
            bb[nt] = sB2[(warpN * 4 + nt) * 32 + lane];
        #pragma unroll
        for (int mt = 0; mt < 4; mt++)
            #pragma unroll
            for (int nt = 0; nt < 4; nt++)
                mma_f16(acc[mt][nt], (const uint32_t*)&ah[mt], (const uint32_t*)&bb[nt]);
    }

    const int cb0 = n0 + warpN * 32 + (lane & 3) * 2;
    const float s = g_scale;
    #pragma unroll
    for (int mt = 0; mt < 4; mt++) {
        const int m16g = m16base + warpM * 4 + mt;
        #pragma unroll
        for (int j = 0; j < 2; j++) {
            const int cglob = (n0 >> 4) + warpN * 2 + j;
            float v0[4], v1[4];
            #pragma unroll
            for (int r = 0; r < 4; r++) {
                int col = cb0 + 2 * j * 8 + (r & 1);
                v0[r] = fmaxf(fmaf(s, acc[mt][2 * j][r], bias[col]), 0.f);
                v1[r] = fmaxf(fmaf(s, acc[mt][2 * j + 1][r], bias[col + 8]), 0.f);
            }
            uint4 hi;
            hi.x = packh(v0[0], v0[1]); hi.y = packh(v0[2], v0[3]);
            hi.z = packh(v1[0], v1[1]); hi.w = packh(v1[2], v1[3]);
            g_pbf[(size_t)m16g * 512 + cglob * 32 + lane] = hi;
        }
    }
}

// ---------------------------------------------------------------------------
// Fused logit GEMM + mask + softmax — warp-autonomous pipeline (tail-fixed).
// CTA M=32, N=1024, 512 thr (16 warps), warp tile 32x64 (warp-private B).
// Per-warp 4-slot cp.async ring, depth 3 in flight; NO CTA barriers in the
// mainloop. TAIL FIX: at chunk c the wait depth is min(2, 15-c) so the
// current chunk is always guaranteed complete (R11 bug: fixed wait 2 left
// chunks 14,15 unwaited -> data race -> rel_err 2.4e-2).
// SMEM (uint4): A [0,1024)  B warp w ring at [1024 + w*512), 4 stages x 128.
// ---------------------------------------------------------------------------
#define FSMEM_BYTES ((1024 + 16 * 512) * 16)   // 147456

__global__ __launch_bounds__(512, 1) void logit_softmax(float* __restrict__ out) {
    extern __shared__ uint32_t sm[];
    const uint32_t sbase = smem_u32(sm);
    const int t = threadIdx.x;
    const int warp = t >> 5, lane = t & 31;
    const int z = blockIdx.y, m0 = blockIdx.x * 32;
    float* Ow = out + (size_t)z * UNUM * ENUM;

    // ---- A: plain load once (1024 uint4 = 16KB) ----
    uint4* sA = (uint4*)sm;
    {
        const uint4* asrc = g_pbf + (size_t)(z * 64 + blockIdx.x * 2) * 512;
        sA[t] = asrc[t];
        sA[512 + t] = asrc[512 + t];
    }
    __syncthreads();

    float acc[2][8][4];
    #pragma unroll
    for (int mi = 0; mi < 2; mi++)
        #pragma unroll
        for (int nt = 0; nt < 8; nt++)
            #pragma unroll
            for (int r = 0; r < 4; r++) acc[mi][nt][r] = 0.f;

    // per-warp B ring
    const uint4* ebase = (const uint4*)(g_ebf2 + (size_t)z * 16 * 4096);
    const uint32_t wring = sbase + (1024 + warp * 512) * 16;
    auto issueB = [&](int c) {
        const uint4* src = ebase + c * 2048 + warp * 128;
        const uint32_t stg = wring + (c & 3) * 128 * 16;
        #pragma unroll
        for (int i = 0; i < 4; i++)
            CP16(stg + (lane + i * 32) * 16, src + lane + i * 32);
        CP_COMMIT();
    };
    issueB(0);
    issueB(1);
    issueB(2);

    #pragma unroll 1
    for (int c = 0; c < 16; c++) {
        // tail-aware wait: guarantee chunk c landed.
        if (c <= 13)      CP_WAIT2();
        else if (c == 14) CP_WAIT1();
        else              CP_WAIT0();
        __syncwarp();
        if (c + 3 < 16) issueB(c + 3);

        const uint2* Bu = (const uint2*)((const uint4*)sm + 1024 + warp * 512 + (c & 3) * 128);
        uint4 ah0 = sA[c * 32 + lane];
        uint4 ah1 = sA[512 + c * 32 + lane];
        #pragma unroll
        for (int nt = 0; nt < 8; nt++) {
            uint2 b = Bu[nt * 32 + lane];
            uint32_t br[2] = { b.x, b.y };
            mma_f16(acc[0][nt], (const uint32_t*)&ah0, br);
            mma_f16(acc[1][nt], (const uint32_t*)&ah1, br);
        }
    }

    // ---- scale + mask + per-lane row max ----
    const int ne = g_ne[z];
    const int lr = lane >> 2;
    float rmax[4] = { -FLT_MAX, -FLT_MAX, -FLT_MAX, -FLT_MAX };
    #pragma unroll
    for (int mi = 0; mi < 2; mi++)
        #pragma unroll
        for (int nt = 0; nt < 8; nt++) {
            int colb = warp * 64 + nt * 8 + (lane & 3) * 2;
            float p0 = (colb >= ne) ? 1e9f : 0.f;
            float p1 = (colb + 1 >= ne) ? 1e9f : 0.f;
            acc[mi][nt][0] = acc[mi][nt][0] * 0.0625f - p0;
            acc[mi][nt][1] = acc[mi][nt][1] * 0.0625f - p1;
            acc[mi][nt][2] = acc[mi][nt][2] * 0.0625f - p0;
            acc[mi][nt][3] = acc[mi][nt][3] * 0.0625f - p1;
            rmax[2 * mi]     = fmaxf(rmax[2 * mi],     fmaxf(acc[mi][nt][0], acc[mi][nt][1]));
            rmax[2 * mi + 1] = fmaxf(rmax[2 * mi + 1], fmaxf(acc[mi][nt][2], acc[mi][nt][3]));
        }
    #pragma unroll
    for (int j = 0; j < 4; j++) {
        rmax[j] = fmaxf(rmax[j], __shfl_xor_sync(0xffffffffu, rmax[j], 1));
        rmax[j] = fmaxf(rmax[j], __shfl_xor_sync(0xffffffffu, rmax[j], 2));
    }

    __syncthreads();                        // all warps done; B rings dead
    float* pmax = (float*)(sm + 4096);      // [32 rows][16 warps]
    float* psum = pmax + 512;
    if ((lane & 3) == 0) {
        #pragma unroll
        for (int j = 0; j < 4; j++) pmax[(lr + j * 8) * 16 + warp] = rmax[j];
    }
    __syncthreads();
    float rm[4];
    #pragma unroll
    for (int j = 0; j < 4; j++) {
        float m = pmax[(lr + j * 8) * 16];
        #pragma unroll
        for (int w = 1; w < 16; w++) m = fmaxf(m, pmax[(lr + j * 8) * 16 + w]);
        rm[j] = m;
    }

    float rs[4] = { 0.f, 0.f, 0.f, 0.f };
    #pragma unroll
    for (int mi = 0; mi < 2; mi++)
        #pragma unroll
        for (int nt = 0; nt < 8; nt++) {
            acc[mi][nt][0] = __expf(acc[mi][nt][0] - rm[2 * mi]);
            acc[mi][nt][1] = __expf(acc[mi][nt][1] - rm[2 * mi]);
            acc[mi][nt][2] = __expf(acc[mi][nt][2] - rm[2 * mi + 1]);
            acc[mi][nt][3] = __expf(acc[mi][nt][3] - rm[2 * mi + 1]);
            rs[2 * mi]     += acc[mi][nt][0] + acc[mi][nt][1];
            rs[2 * mi + 1] += acc[mi][nt][2] + acc[mi][nt][3];
        }
    #pragma unroll
    for (int j = 0; j < 4; j++) {
        rs[j] += __shfl_xor_sync(0xffffffffu, rs[j], 1);
        rs[j] += __shfl_xor_sync(0xffffffffu, rs[j], 2);
    }
    if ((lane & 3) == 0) {
        #pragma unroll
        for (int j = 0; j < 4; j++) psum[(lr + j * 8) * 16 + warp] = rs[j];
    }
    __syncthreads();
    float inv[4];
    #pragma unroll
    for (int j = 0; j < 4; j++) {
        float s = 0.f;
        #pragma unroll
        for (int w = 0; w < 16; w++) s += psum[(lr + j * 8) * 16 + w];
        inv[j] = 1.f / s;
    }

    // ---- normalize + store ----
    #pragma unroll
    for (int mi = 0; mi < 2; mi++) {
        float* r0 = Ow + (size_t)(m0 + mi * 16 + lr) * ENUM;
        float* r1 = Ow + (size_t)(m0 + mi * 16 + lr + 8) * ENUM;
        #pragma unroll
        for (int nt = 0; nt < 8; nt++) {
            int colb = warp * 64 + nt * 8 + (lane & 3) * 2;
            *(float2*)(r0 + colb) =
                make_float2(acc[mi][nt][0] * inv[2 * mi], acc[mi][nt][1] * inv[2 * mi]);
            *(float2*)(r1 + colb) =
                make_float2(acc[mi][nt][2] * inv[2 * mi + 1], acc[mi][nt][3] * inv[2 * mi + 1]);
        }
    }
}

// ---------------------------------------------------------------------------
extern "C" void kernel_launch(void* const* d_in, const int* in_sizes, int n_in,
                              void* d_out, int out_size) {
    const float* ufeat = (const float*)d_in[0];   // [64,1024,512]
    const float* efeat = (const float*)d_in[1];   // [64,1024,256]
    const int*   neptr = (const int*)d_in[2];     // [64] int32 or int64
    const float* v     = (const float*)d_in[3];   // [256,512]
    const float* g     = (const float*)d_in[4];   // scalar
    const float* bias  = (const float*)d_in[5];   // [256]
    float* out = (float*)d_out;                   // [64,1024,1024]

    cudaFuncSetAttribute(proj_gemm, cudaFuncAttributeMaxDynamicSharedMemorySize, PSMEM_BYTES);
    cudaFuncSetAttribute(logit_softmax, cudaFuncAttributeMaxDynamicSharedMemorySize, FSMEM_BYTES);

    prep_partial<<<32, 1024>>>(v);
    vconv_full<<<128, 256>>>(v);
    conv_all<<<32768, 256>>>(ufeat, efeat, g, neptr);
    proj_gemm<<<dim3(2, 512), 256, PSMEM_BYTES>>>(bias);
    logit_softmax<<<dim3(UNUM / 32, BATCH), 512, FSMEM_BYTES>>>(out);
}

// round 14
// speedup vs baseline: 1.1479x; 1.1479x over previous
#include <cuda_runtime.h>
#include <cstdint>
#include <cfloat>

#define BATCH 64
#define UNUM  1024
#define ENUM  1024
#define UFD   512
#define EFD   256

__device__ float g_scale;
__device__ float g_part[32];
__device__ int   g_ne[BATCH];
__device__ uint2 g_ebf2[(size_t)BATCH * 16 * 128 * 32];  // efeat B-frags fp16 hi
__device__ uint4 g_ubf2[(size_t)4096 * 32 * 32];         // ufeat A-frags fp16 hi
__device__ uint2 g_vbf2b[(size_t)32 * 32 * 32];          // v B-frags fp16 hi
__device__ uint4 g_pbf[(size_t)4096 * 512];              // proj A-frags fp16 hi

// ---------------------------------------------------------------------------
// helpers
// ---------------------------------------------------------------------------
__device__ __forceinline__ uint32_t packh(float x0, float x1) {
    uint32_t r;   // {hi16: fp16(x1), lo16: fp16(x0)}
    asm("cvt.rn.f16x2.f32 %0, %1, %2;" : "=r"(r) : "f"(x1), "f"(x0));
    return r;
}
__device__ __forceinline__ void mma_f16(float* d, const uint32_t* a, const uint32_t* b) {
    asm volatile(
        "mma.sync.aligned.m16n8k16.row.col.f32.f16.f16.f32 "
        "{%0,%1,%2,%3}, {%4,%5,%6,%7}, {%8,%9}, {%0,%1,%2,%3};"
        : "+f"(d[0]), "+f"(d[1]), "+f"(d[2]), "+f"(d[3])
        : "r"(a[0]), "r"(a[1]), "r"(a[2]), "r"(a[3]), "r"(b[0]), "r"(b[1]));
}
__device__ __forceinline__ uint32_t smem_u32(const void* p) {
    uint32_t a;
    asm("{ .reg .u64 t; cvta.to.shared.u64 t, %1; cvt.u32.u64 %0, t; }" : "=r"(a) : "l"(p));
    return a;
}
#define CP16(dst, src) \
    asm volatile("cp.async.cg.shared.global [%0], [%1], 16;" :: "r"(dst), "l"(src) : "memory")
#define CP_COMMIT() asm volatile("cp.async.commit_group;" ::: "memory")
#define CP_WAIT1()  asm volatile("cp.async.wait_group 1;" ::: "memory")
#define CP_WAIT0()  asm volatile("cp.async.wait_group 0;" ::: "memory")

// ---------------------------------------------------------------------------
// prep_partial: ||v||^2 partials
// ---------------------------------------------------------------------------
__global__ __launch_bounds__(1024) void prep_partial(const float* __restrict__ v) {
    __shared__ float wsum[32];
    int tid = threadIdx.x, b = blockIdx.x;
    float s = 0.f;
    #pragma unroll
    for (int i = 0; i < 4; i++) {
        float x = v[b * 4096 + i * 1024 + tid];
        s += x * x;
    }
    #pragma unroll
    for (int o = 16; o; o >>= 1) s += __shfl_xor_sync(0xffffffffu, s, o);
    if ((tid & 31) == 0) wsum[tid >> 5] = s;
    __syncthreads();
    if (tid == 0) {
        float tot = 0.f;
        #pragma unroll
        for (int w = 0; w < 32; w++) tot += wsum[w];
        g_part[b] = tot;
    }
}

// ---------------------------------------------------------------------------
// uvconv: finalize + uconv(hi) + vconv(hi) in one launch.
// blocks [0,16384): ufeat -> A-frags; [16384,16512): v -> B-frags.
// ---------------------------------------------------------------------------
__global__ __launch_bounds__(256) void uvconv(const float* __restrict__ uf,
                                              const float* __restrict__ v,
                                              const float* __restrict__ g,
                                              const int* __restrict__ ne32) {
    const uint32_t b = blockIdx.x;
    const int t = threadIdx.x;
    if (b == 0 && t == 0) {
        float tot = 0.f;
        #pragma unroll
        for (int i = 0; i < 32; i++) tot += g_part[i];
        g_scale = g[0] / sqrtf(tot);
        bool is64 = true;
        for (int i = 0; i < 32; i++)
            if (ne32[2 * i + 1] != 0) { is64 = false; break; }
        for (int i = 0; i < BATCH; i++) g_ne[i] = is64 ? ne32[2 * i] : ne32[i];
    }

    if (b < 16384) {                    // ---- uconv (hi only) ----
        uint32_t gid = b * 256 + t;
        int lane = gid & 31;
        int c    = (gid >> 5) & 31;
        int m16  = gid >> 10;
        int r    = m16 * 16 + (lane >> 2);
        int k0   = c * 16 + (lane & 3) * 2;
        const float* s0 = uf + (size_t)r * UFD;
        const float* s1 = uf + (size_t)(r + 8) * UFD;
        float2 a0 = *(const float2*)(s0 + k0);
        float2 a1 = *(const float2*)(s1 + k0);
        float2 a2 = *(const float2*)(s0 + k0 + 8);
        float2 a3 = *(const float2*)(s1 + k0 + 8);
        uint4 hi;
        hi.x = packh(a0.x, a0.y); hi.y = packh(a1.x, a1.y);
        hi.z = packh(a2.x, a2.y); hi.w = packh(a3.x, a3.y);
        g_ubf2[gid] = hi;
    } else {                            // ---- vconv (hi only) ----
        uint32_t gid = (b - 16384) * 256 + t;   // 32768 gids
        int lane = gid & 31;
        int n8   = (gid >> 5) & 31;
        int c    = gid >> 10;
        int n    = n8 * 8 + (lane >> 2);
        int k0   = c * 16 + (lane & 3) * 2;
        const float* src = v + (size_t)n * UFD;
        float2 f0 = *(const float2*)(src + k0);
        float2 f1 = *(const float2*)(src + k0 + 8);
        uint2 o;
        o.x = packh(f0.x, f0.y);
        o.y = packh(f1.x, f1.y);
        g_vbf2b[(size_t)(c * 32 + n8) * 32 + lane] = o;
    }
}

// ---------------------------------------------------------------------------
// proj_econv: blocks [0,1024) = proj GEMM (tile 128x128, fp16 1-MMA, 3-stage
// cp.async -> g_pbf A-frags); blocks [1024,17408) = econv (efeat -> B-frags,
// fp16 hi). Independent work co-resident: proj is tensor/latency-bound,
// econv pure-memory -> econv hides under proj.
// ---------------------------------------------------------------------------
#define PSMEM_BYTES (3 * 512 * 16)   // 24 KB

__global__ __launch_bounds__(256, 2) void proj_econv(const float* __restrict__ bias,
                                                     const float* __restrict__ ef) {
    const int t = threadIdx.x;

    if (blockIdx.x >= 1024) {           // ================= econv =================
        uint32_t gid = (blockIdx.x - 1024) * 256 + t;
        int lane = gid & 31;
        int n8   = (gid >> 5) & 127;
        int c    = (gid >> 12) & 15;
        int z    = gid >> 16;
        int n    = n8 * 8 + (lane >> 2);
        int k0   = c * 16 + (lane & 3) * 2;
        const float* src = ef + ((size_t)z * ENUM + n) * EFD;
        float2 f0 = *(const float2*)(src + k0);
        float2 f1 = *(const float2*)(src + k0 + 8);
        uint2 o;
        o.x = packh(f0.x, f0.y);
        o.y = packh(f1.x, f1.y);
        g_ebf2[gid] = o;
        return;
    }

    // ================= proj GEMM =================
    extern __shared__ uint4 su[];
    const uint32_t sbase = smem_u32(su);
    const int warp = t >> 5, lane = t & 31;
    const int warpM = warp >> 2, warpN = warp & 3;
    const int bx = blockIdx.x & 1, by = blockIdx.x >> 1;
    const int n0 = bx * 128;
    const int m16base = by * 8;
    const int n8base = bx * 16;

    float acc[4][4][4];
    #pragma unroll
    for (int i = 0; i < 4; i++)
        #pragma unroll
        for (int j = 0; j < 4; j++)
            #pragma unroll
            for (int r = 0; r < 4; r++) acc[i][j][r] = 0.f;

    constexpr int NCH = UFD / 16;   // 32

    auto issue = [&](int c) {
        const int s = ((unsigned)c) % 3;
        const uint32_t stb = sbase + s * 8192;
        {   // A: 256 uint4
            int m16l = t >> 5, ln = t & 31;
            const uint4* src = g_ubf2 + (size_t)((m16base + m16l) * 32 + c) * 32 + ln;
            CP16(stb + t * 16, src);
        }
        {   // B: 256 uint4
            const uint4* src = (const uint4*)(g_vbf2b + (size_t)(c * 32 + n8base) * 32) + t;
            CP16(stb + (256 + t) * 16, src);
        }
        CP_COMMIT();
    };

    issue(0);
    issue(1);
    #pragma unroll 1
    for (int c = 0; c < NCH; c++) {
        if (c == NCH - 1) CP_WAIT0(); else CP_WAIT1();
        __syncthreads();
        if (c + 2 < NCH) issue(c + 2);

        const uint4* st = su + ((unsigned)c % 3) * 512;
        const uint2* sB2 = (const uint2*)(st + 256);
        uint4 ah[4];
        uint2 bb[4];
        #pragma unroll
        for (int mt = 0; mt < 4; mt++)
            ah[mt] = st[(warpM * 4 + mt) * 32 + lane];
        #pragma unroll
        for (int nt = 0; nt < 4; nt++)
            bb[nt] = sB2[(warpN * 4 + nt) * 32 + lane];
        #pragma unroll
        for (int mt = 0; mt < 4; mt++)
            #pragma unroll
            for (int nt = 0; nt < 4; nt++)
                mma_f16(acc[mt][nt], (const uint32_t*)&ah[mt], (const uint32_t*)&bb[nt]);
    }

    const int cb0 = n0 + warpN * 32 + (lane & 3) * 2;
    const float s = g_scale;
    #pragma unroll
    for (int mt = 0; mt < 4; mt++) {
        const int m16g = m16base + warpM * 4 + mt;
        #pragma unroll
        for (int j = 0; j < 2; j++) {
            const int cglob = (n0 >> 4) + warpN * 2 + j;
            float v0[4], v1[4];
            #pragma unroll
            for (int r = 0; r < 4; r++) {
                int col = cb0 + 2 * j * 8 + (r & 1);
                v0[r] = fmaxf(fmaf(s, acc[mt][2 * j][r], bias[col]), 0.f);
                v1[r] = fmaxf(fmaf(s, acc[mt][2 * j + 1][r], bias[col + 8]), 0.f);
            }
            uint4 hi;
            hi.x = packh(v0[0], v0[1]); hi.y = packh(v0[2], v0[3]);
            hi.z = packh(v1[0], v1[1]); hi.w = packh(v1[2], v1[3]);
            g_pbf[(size_t)m16g * 512 + cglob * 32 + lane] = hi;
        }
    }
}

// ---------------------------------------------------------------------------
// Fused logit GEMM + mask + softmax (R10 version — best measured, 206us).
// CTA M=32, N=1024, 512 thr (1m x 16n warps), 2 chunks (32 k) per step.
// SMEM (uint4): A [0,1024)  B stage s at [1024 + s*4096) (3 stages, 64KB each)
// ---------------------------------------------------------------------------
#define FSMEM_BYTES ((1024 + 3 * 4096) * 16)   // 212992

__global__ __launch_bounds__(512, 1) void logit_softmax(float* __restrict__ out) {
    extern __shared__ uint32_t sm[];
    const uint32_t sbase = smem_u32(sm);
    const int t = threadIdx.x;
    const int warp = t >> 5, lane = t & 31;
    const int z = blockIdx.y, m0 = blockIdx.x * 32;
    float* Ow = out + (size_t)z * UNUM * ENUM;

    // ---- A: cp.async pre-made hi fragments (1024 uint4) ----
    {
        const uint4* asrc = g_pbf + (size_t)(z * 64 + blockIdx.x * 2) * 512;
        #pragma unroll
        for (int i = 0; i < 2; i++) {
            int f = t + i * 512;
            CP16(sbase + f * 16, asrc + f);
        }
        CP_COMMIT();
    }

    float acc[2][8][4];
    #pragma unroll
    for (int mi = 0; mi < 2; mi++)
        #pragma unroll
        for (int nt = 0; nt < 8; nt++)
            #pragma unroll
            for (int r = 0; r < 4; r++) acc[mi][nt][r] = 0.f;

    const uint4* ebase = (const uint4*)(g_ebf2 + (size_t)z * 16 * 4096);
    auto issueB = [&](int ci) {        // ci = chunk-pair index 0..7
        const uint4* src = ebase + ci * 4096;
        const uint32_t bb = sbase + (1024 + ((unsigned)ci % 3) * 4096) * 16;
        #pragma unroll
        for (int i = 0; i < 8; i++) {
            int f = t + i * 512;
            CP16(bb + f * 16, src + f);
        }
        CP_COMMIT();
    };
    issueB(0);
    issueB(1);

    const uint4* sA4 = (const uint4*)sm;

    #pragma unroll 1
    for (int ci = 0; ci < 8; ci++) {
        if (ci == 7) CP_WAIT0(); else CP_WAIT1();
        __syncthreads();
        if (ci + 2 < 8) issueB(ci + 2);

        const uint2* Bu = (const uint2*)(sA4 + 1024 + ((unsigned)ci % 3) * 4096);
        #pragma unroll
        for (int cc = 0; cc < 2; cc++) {
            const int c = ci * 2 + cc;
            uint4 ah0 = sA4[c * 32 + lane];
            uint4 ah1 = sA4[512 + c * 32 + lane];
            #pragma unroll
            for (int nt = 0; nt < 8; nt++) {
                uint2 b = Bu[cc * 4096 + (warp * 8 + nt) * 32 + lane];
                uint32_t br[2] = { b.x, b.y };
                mma_f16(acc[0][nt], (const uint32_t*)&ah0, br);
                mma_f16(acc[1][nt], (const uint32_t*)&ah1, br);
            }
        }
    }

    // ---- scale + mask + per-lane row max ----
    const int ne = g_ne[z];
    const int lr = lane >> 2;
    float rmax[4] = { -FLT_MAX, -FLT_MAX, -FLT_MAX, -FLT_MAX };
    #pragma unroll
    for (int mi = 0; mi < 2; mi++)
        #pragma unroll
        for (int nt = 0; nt < 8; nt++) {
            int colb = warp * 64 + nt * 8 + (lane & 3) * 2;
            float p0 = (colb >= ne) ? 1e9f : 0.f;
            float p1 = (colb + 1 >= ne) ? 1e9f : 0.f;
            acc[mi][nt][0] = acc[mi][nt][0] * 0.0625f - p0;
            acc[mi][nt][1] = acc[mi][nt][1] * 0.0625f - p1;
            acc[mi][nt][2] = acc[mi][nt][2] * 0.0625f - p0;
            acc[mi][nt][3] = acc[mi][nt][3] * 0.0625f - p1;
            rmax[2 * mi]     = fmaxf(rmax[2 * mi],     fmaxf(acc[mi][nt][0], acc[mi][nt][1]));
            rmax[2 * mi + 1] = fmaxf(rmax[2 * mi + 1], fmaxf(acc[mi][nt][2], acc[mi][nt][3]));
        }
    #pragma unroll
    for (int j = 0; j < 4; j++) {
        rmax[j] = fmaxf(rmax[j], __shfl_xor_sync(0xffffffffu, rmax[j], 1));
        rmax[j] = fmaxf(rmax[j], __shfl_xor_sync(0xffffffffu, rmax[j], 2));
    }

    __syncthreads();                        // B stage 0 dead; reuse as scratch
    float* pmax = (float*)(sm + 4096);      // [32 rows][16 warps]
    float* psum = pmax + 512;
    if ((lane & 3) == 0) {
        #pragma unroll
        for (int j = 0; j < 4; j++) pmax[(lr + j * 8) * 16 + warp] = rmax[j];
    }
    __syncthreads();
    float rm[4];
    #pragma unroll
    for (int j = 0; j < 4; j++) {
        float m = pmax[(lr + j * 8) * 16];
        #pragma unroll
        for (int w = 1; w < 16; w++) m = fmaxf(m, pmax[(lr + j * 8) * 16 + w]);
        rm[j] = m;
    }

    float rs[4] = { 0.f, 0.f, 0.f, 0.f };
    #pragma unroll
    for (int mi = 0; mi < 2; mi++)
        #pragma unroll
        for (int nt = 0; nt < 8; nt++) {
            acc[mi][nt][0] = __expf(acc[mi][nt][0] - rm[2 * mi]);
            acc[mi][nt][1] = __expf(acc[mi][nt][1] - rm[2 * mi]);
            acc[mi][nt][2] = __expf(acc[mi][nt][2] - rm[2 * mi + 1]);
            acc[mi][nt][3] = __expf(acc[mi][nt][3] - rm[2 * mi + 1]);
            rs[2 * mi]     += acc[mi][nt][0] + acc[mi][nt][1];
            rs[2 * mi + 1] += acc[mi][nt][2] + acc[mi][nt][3];
        }
    #pragma unroll
    for (int j = 0; j < 4; j++) {
        rs[j] += __shfl_xor_sync(0xffffffffu, rs[j], 1);
        rs[j] += __shfl_xor_sync(0xffffffffu, rs[j], 2);
    }
    if ((lane & 3) == 0) {
        #pragma unroll
        for (int j = 0; j < 4; j++) psum[(lr + j * 8) * 16 + warp] = rs[j];
    }
    __syncthreads();
    float inv[4];
    #pragma unroll
    for (int j = 0; j < 4; j++) {
        float s = 0.f;
        #pragma unroll
        for (int w = 0; w < 16; w++) s += psum[(lr + j * 8) * 16 + w];
        inv[j] = 1.f / s;
    }

    // ---- normalize + store ----
    #pragma unroll
    for (int mi = 0; mi < 2; mi++) {
        float* r0 = Ow + (size_t)(m0 + mi * 16 + lr) * ENUM;
        float* r1 = Ow + (size_t)(m0 + mi * 16 + lr + 8) * ENUM;
        #pragma unroll
        for (int nt = 0; nt < 8; nt++) {
            int colb = warp * 64 + nt * 8 + (lane & 3) * 2;
            *(float2*)(r0 + colb) =
                make_float2(acc[mi][nt][0] * inv[2 * mi], acc[mi][nt][1] * inv[2 * mi]);
            *(float2*)(r1 + colb) =
                make_float2(acc[mi][nt][2] * inv[2 * mi + 1], acc[mi][nt][3] * inv[2 * mi + 1]);
        }
    }
}

// ---------------------------------------------------------------------------
extern "C" void kernel_launch(void* const* d_in, const int* in_sizes, int n_in,
                              void* d_out, int out_size) {
    const float* ufeat = (const float*)d_in[0];   // [64,1024,512]
    const float* efeat = (const float*)d_in[1];   // [64,1024,256]
    const int*   neptr = (const int*)d_in[2];     // [64] int32 or int64
    const float* v     = (const float*)d_in[3];   // [256,512]
    const float* g     = (const float*)d_in[4];   // scalar
    const float* bias  = (const float*)d_in[5];   // [256]
    float* out = (float*)d_out;                   // [64,1024,1024]

    cudaFuncSetAttribute(proj_econv, cudaFuncAttributeMaxDynamicSharedMemorySize, PSMEM_BYTES);
    cudaFuncSetAttribute(logit_softmax, cudaFuncAttributeMaxDynamicSharedMemorySize, FSMEM_BYTES);

    prep_partial<<<32, 1024>>>(v);
    uvconv<<<16512, 256>>>(ufeat, v, g, neptr);
    proj_econv<<<17408, 256, PSMEM_BYTES>>>(bias, efeat);   // proj ∥ econv
    logit_softmax<<<dim3(UNUM / 32, BATCH), 512, FSMEM_BYTES>>>(out);
}

// round 16
// speedup vs baseline: 1.1890x; 1.0358x over previous
#include <cuda_runtime.h>
#include <cstdint>
#include <cfloat>

#define BATCH 64
#define UNUM  1024
#define ENUM  1024
#define UFD   512
#define EFD   256

__device__ float g_scale;
__device__ float g_part[32];
__device__ int   g_ne[BATCH];
__device__ uint2 g_ebf2[(size_t)BATCH * 16 * 128 * 32];  // efeat B-frags fp16 hi
__device__ uint4 g_ubf2[(size_t)4096 * 32 * 32];         // ufeat A-frags fp16 hi
__device__ uint2 g_vbf2b[(size_t)32 * 32 * 32];          // v B-frags fp16 hi
__device__ uint4 g_pbf[(size_t)4096 * 512];              // proj A-frags fp16 hi

// ---------------------------------------------------------------------------
// helpers
// ---------------------------------------------------------------------------
__device__ __forceinline__ uint32_t packh(float x0, float x1) {
    uint32_t r;   // {hi16: fp16(x1), lo16: fp16(x0)}
    asm("cvt.rn.f16x2.f32 %0, %1, %2;" : "=r"(r) : "f"(x1), "f"(x0));
    return r;
}
__device__ __forceinline__ void mma_f16(float* d, const uint32_t* a, const uint32_t* b) {
    asm volatile(
        "mma.sync.aligned.m16n8k16.row.col.f32.f16.f16.f32 "
        "{%0,%1,%2,%3}, {%4,%5,%6,%7}, {%8,%9}, {%0,%1,%2,%3};"
        : "+f"(d[0]), "+f"(d[1]), "+f"(d[2]), "+f"(d[3])
        : "r"(a[0]), "r"(a[1]), "r"(a[2]), "r"(a[3]), "r"(b[0]), "r"(b[1]));
}
__device__ __forceinline__ uint32_t smem_u32(const void* p) {
    uint32_t a;
    asm("{ .reg .u64 t; cvta.to.shared.u64 t, %1; cvt.u32.u64 %0, t; }" : "=r"(a) : "l"(p));
    return a;
}
#define CP16(dst, src) \
    asm volatile("cp.async.cg.shared.global [%0], [%1], 16;" :: "r"(dst), "l"(src) : "memory")
#define CP_COMMIT() asm volatile("cp.async.commit_group;" ::: "memory")
#define CP_WAIT2()  asm volatile("cp.async.wait_group 2;" ::: "memory")
#define CP_WAIT1()  asm volatile("cp.async.wait_group 1;" ::: "memory")
#define CP_WAIT0()  asm volatile("cp.async.wait_group 0;" ::: "memory")

// ---------------------------------------------------------------------------
// prep_partial: ||v||^2 partials
// ---------------------------------------------------------------------------
__global__ __launch_bounds__(1024) void prep_partial(const float* __restrict__ v) {
    __shared__ float wsum[32];
    int tid = threadIdx.x, b = blockIdx.x;
    float s = 0.f;
    #pragma unroll
    for (int i = 0; i < 4; i++) {
        float x = v[b * 4096 + i * 1024 + tid];
        s += x * x;
    }
    #pragma unroll
    for (int o = 16; o; o >>= 1) s += __shfl_xor_sync(0xffffffffu, s, o);
    if ((tid & 31) == 0) wsum[tid >> 5] = s;
    __syncthreads();
    if (tid == 0) {
        float tot = 0.f;
        #pragma unroll
        for (int w = 0; w < 32; w++) tot += wsum[w];
        g_part[b] = tot;
    }
}

// ---------------------------------------------------------------------------
// conv_all: finalize + uconv(hi) + vconv(hi) + econv(hi), one launch.
// blocks [0,16384): ufeat; [16384,16512): v; [16512,32896): efeat.
// ---------------------------------------------------------------------------
__global__ __launch_bounds__(256) void conv_all(const float* __restrict__ uf,
                                                const float* __restrict__ v,
                                                const float* __restrict__ ef,
                                                const float* __restrict__ g,
                                                const int* __restrict__ ne32) {
    const uint32_t b = blockIdx.x;
    const int t = threadIdx.x;
    if (b == 0 && t == 0) {
        float tot = 0.f;
        #pragma unroll
        for (int i = 0; i < 32; i++) tot += g_part[i];
        g_scale = g[0] / sqrtf(tot);
        bool is64 = true;
        for (int i = 0; i < 32; i++)
            if (ne32[2 * i + 1] != 0) { is64 = false; break; }
        for (int i = 0; i < BATCH; i++) g_ne[i] = is64 ? ne32[2 * i] : ne32[i];
    }

    if (b < 16384) {                    // ---- uconv (hi only) ----
        uint32_t gid = b * 256 + t;
        int lane = gid & 31;
        int c    = (gid >> 5) & 31;
        int m16  = gid >> 10;
        int r    = m16 * 16 + (lane >> 2);
        int k0   = c * 16 + (lane & 3) * 2;
        const float* s0 = uf + (size_t)r * UFD;
        const float* s1 = uf + (size_t)(r + 8) * UFD;
        float2 a0 = *(const float2*)(s0 + k0);
        float2 a1 = *(const float2*)(s1 + k0);
        float2 a2 = *(const float2*)(s0 + k0 + 8);
        float2 a3 = *(const float2*)(s1 + k0 + 8);
        uint4 hi;
        hi.x = packh(a0.x, a0.y); hi.y = packh(a1.x, a1.y);
        hi.z = packh(a2.x, a2.y); hi.w = packh(a3.x, a3.y);
        g_ubf2[gid] = hi;
    } else if (b < 16512) {             // ---- vconv (hi only), 32768 gids ----
        uint32_t gid = (b - 16384) * 256 + t;
        int lane = gid & 31;
        int n8   = (gid >> 5) & 31;
        int c    = gid >> 10;
        int n    = n8 * 8 + (lane >> 2);
        int k0   = c * 16 + (lane & 3) * 2;
        const float* src = v + (size_t)n * UFD;
        float2 f0 = *(const float2*)(src + k0);
        float2 f1 = *(const float2*)(src + k0 + 8);
        uint2 o;
        o.x = packh(f0.x, f0.y);
        o.y = packh(f1.x, f1.y);
        g_vbf2b[(size_t)(c * 32 + n8) * 32 + lane] = o;
    } else {                            // ---- econv (hi only) ----
        uint32_t gid = (b - 16512) * 256 + t;
        int lane = gid & 31;
        int n8   = (gid >> 5) & 127;
        int c    = (gid >> 12) & 15;
        int z    = gid >> 16;
        int n    = n8 * 8 + (lane >> 2);
        int k0   = c * 16 + (lane & 3) * 2;
        const float* src = ef + ((size_t)z * ENUM + n) * EFD;
        float2 f0 = *(const float2*)(src + k0);
        float2 f1 = *(const float2*)(src + k0 + 8);
        uint2 o;
        o.x = packh(f0.x, f0.y);
        o.y = packh(f1.x, f1.y);
        g_ebf2[gid] = o;
    }
}

// ---------------------------------------------------------------------------
// proj GEMM: B-RESIDENT version. relu(g_scale*(ufeat@v^T)+bias) -> g_pbf.
// Tile 256(m) x 128(n), 512 thr = 16 warps (4m x 4n), warp tile 64x32.
// B slice (this n-tile's full v fragments, 128KB) cp.async'd ONCE at start;
// A streams 8KB/chunk through a 4-stage ring (depth 3 in flight, tail-aware
// waits: entry pending at chunk c = {c,c+1,c+2} -> WAIT2 (c<=29) / WAIT1
// (c==30) / WAIT0 (c==31); the B group retires with chunk 0's wait).
// SMEM (uint4): B [0,8192)   A stage s at [8192 + s*512)   => 160 KB
// ---------------------------------------------------------------------------
#define PSMEM_BYTES ((8192 + 4 * 512) * 16)   // 163840

__global__ __launch_bounds__(512, 1) void proj_gemm(const float* __restrict__ bias) {
    extern __shared__ uint4 su[];
    const uint32_t sbase = smem_u32(su);
    const int t = threadIdx.x;
    const int warp = t >> 5, lane = t & 31;
    const int warpM = warp >> 2, warpN = warp & 3;
    const int bx = blockIdx.x;              // 0..1 (n-tile)
    const int n0 = bx * 128;
    const int n8base = bx * 16;
    const int m16base = blockIdx.y * 16;    // 16 m16 tiles per CTA (M=256)

    float acc[4][4][4];
    #pragma unroll
    for (int i = 0; i < 4; i++)
        #pragma unroll
        for (int j = 0; j < 4; j++)
            #pragma unroll
            for (int r = 0; r < 4; r++) acc[i][j][r] = 0.f;

    // ---- B: load entire n-tile slice once (8192 uint4), one group ----
    {
        #pragma unroll
        for (int i = 0; i < 16; i++) {
            int f = t + i * 512;
            int c = f >> 8, rem = f & 255;   // per chunk: 256 uint4 contiguous
            const uint4* src = (const uint4*)(g_vbf2b + (size_t)(c * 32 + n8base) * 32) + rem;
            CP16(sbase + f * 16, src);
        }
        CP_COMMIT();
    }

    // ---- A stream: 512 uint4 per chunk (16 m16 x 32 lanes) ----
    auto issueA = [&](int c) {
        const uint32_t stb = sbase + (8192 + (c & 3) * 512) * 16;
        const uint4* src = g_ubf2 + (size_t)((m16base + (t >> 5)) * 32 + c) * 32 + (t & 31);
        CP16(stb + t * 16, src);
        CP_COMMIT();
    };
    issueA(0);
    issueA(1);
    issueA(2);

    #pragma unroll 1
    for (int c = 0; c < 32; c++) {
        if (c <= 29)      CP_WAIT2();       // entry pending {c, c+1, c+2}
        else if (c == 30) CP_WAIT1();       // {30, 31}
        else              CP_WAIT0();       // {31}
        __syncthreads();
        if (c + 3 < 32) issueA(c + 3);

        const uint4* sa = su + 8192 + (c & 3) * 512;
        const uint2* sB2 = (const uint2*)su + (size_t)c * 512;
        uint4 ah[4];
        uint2 bb[4];
        #pragma unroll
        for (int mt = 0; mt < 4; mt++)
            ah[mt] = sa[(warpM * 4 + mt) * 32 + lane];
        #pragma unroll
        for (int nt = 0; nt < 4; nt++)
            bb[nt] = sB2[(warpN * 4 + nt) * 32 + lane];
        #pragma unroll
        for (int mt = 0; mt < 4; mt++)
            #pragma unroll
            for (int nt = 0; nt < 4; nt++)
                mma_f16(acc[mt][nt], (const uint32_t*)&ah[mt], (const uint32_t*)&bb[nt]);
    }

    // ---- epilogue: scale+bias+relu, pack into fp16-hi A-fragment form ----
    const int cb0 = n0 + warpN * 32 + (lane & 3) * 2;
    const float s = g_scale;
    #pragma unroll
    for (int mt = 0; mt < 4; mt++) {
        const int m16g = m16base + warpM * 4 + mt;
        #pragma unroll
        for (int j = 0; j < 2; j++) {
            const int cglob = (n0 >> 4) + warpN * 2 + j;
            float v0[4], v1[4];
            #pragma unroll
            for (int r = 0; r < 4; r++) {
                int col = cb0 + 2 * j * 8 + (r & 1);
                v0[r] = fmaxf(fmaf(s, acc[mt][2 * j][r], bias[col]), 0.f);
                v1[r] = fmaxf(fmaf(s, acc[mt][2 * j + 1][r], bias[col + 8]), 0.f);
            }
            uint4 hi;
            hi.x = packh(v0[0], v0[1]); hi.y = packh(v0[2], v0[3]);
            hi.z = packh(v1[0], v1[1]); hi.w = packh(v1[2], v1[3]);
            g_pbf[(size_t)m16g * 512 + cglob * 32 + lane] = hi;
        }
    }
}

// ---------------------------------------------------------------------------
// Fused logit GEMM + mask + softmax (R10 version — best measured).
// CTA M=32, N=1024, 512 thr (1m x 16n warps), 2 chunks (32 k) per step.
// SMEM (uint4): A [0,1024)  B stage s at [1024 + s*4096) (3 stages, 64KB each)
// ---------------------------------------------------------------------------
#define FSMEM_BYTES ((1024 + 3 * 4096) * 16)   // 212992

__global__ __launch_bounds__(512, 1) void logit_softmax(float* __restrict__ out) {
    extern __shared__ uint32_t sm[];
    const uint32_t sbase = smem_u32(sm);
    const int t = threadIdx.x;
    const int warp = t >> 5, lane = t & 31;
    const int z = blockIdx.y, m0 = blockIdx.x * 32;
    float* Ow = out + (size_t)z * UNUM * ENUM;

    // ---- A: cp.async pre-made hi fragments (1024 uint4) ----
    {
        const uint4* asrc = g_pbf + (size_t)(z * 64 + blockIdx.x * 2) * 512;
        #pragma unroll
        for (int i = 0; i < 2; i++) {
            int f = t + i * 512;
            CP16(sbase + f * 16, asrc + f);
        }
        CP_COMMIT();
    }

    float acc[2][8][4];
    #pragma unroll
    for (int mi = 0; mi < 2; mi++)
        #pragma unroll
        for (int nt = 0; nt < 8; nt++)
            #pragma unroll
            for (int r = 0; r < 4; r++) acc[mi][nt][r] = 0.f;

    const uint4* ebase = (const uint4*)(g_ebf2 + (size_t)z * 16 * 4096);
    auto issueB = [&](int ci) {        // ci = chunk-pair index 0..7
        const uint4* src = ebase + ci * 4096;
        const uint32_t bb = sbase + (1024 + ((unsigned)ci % 3) * 4096) * 16;
        #pragma unroll
        for (int i = 0; i < 8; i++) {
            int f = t + i * 512;
            CP16(bb + f * 16, src + f);
        }
        CP_COMMIT();
    };
    issueB(0);
    issueB(1);

    const uint4* sA4 = (const uint4*)sm;

    #pragma unroll 1
    for (int ci = 0; ci < 8; ci++) {
        if (ci == 7) CP_WAIT0(); else CP_WAIT1();
        __syncthreads();
        if (ci + 2 < 8) issueB(ci + 2);

        const uint2* Bu = (const uint2*)(sA4 + 1024 + ((unsigned)ci % 3) * 4096);
        #pragma unroll
        for (int cc = 0; cc < 2; cc++) {
            const int c = ci * 2 + cc;
            uint4 ah0 = sA4[c * 32 + lane];
            uint4 ah1 = sA4[512 + c * 32 + lane];
            #pragma unroll
            for (int nt = 0; nt < 8; nt++) {
                uint2 b = Bu[cc * 4096 + (warp * 8 + nt) * 32 + lane];
                uint32_t br[2] = { b.x, b.y };
                mma_f16(acc[0][nt], (const uint32_t*)&ah0, br);
                mma_f16(acc[1][nt], (const uint32_t*)&ah1, br);
            }
        }
    }

    // ---- scale + mask + per-lane row max ----
    const int ne = g_ne[z];
    const int lr = lane >> 2;
    float rmax[4] = { -FLT_MAX, -FLT_MAX, -FLT_MAX, -FLT_MAX };
    #pragma unroll
    for (int mi = 0; mi < 2; mi++)
        #pragma unroll
        for (int nt = 0; nt < 8; nt++) {
            int colb = warp * 64 + nt * 8 + (lane & 3) * 2;
            float p0 = (colb >= ne) ? 1e9f : 0.f;
            float p1 = (colb + 1 >= ne) ? 1e9f : 0.f;
            acc[mi][nt][0] = acc[mi][nt][0] * 0.0625f - p0;
            acc[mi][nt][1] = acc[mi][nt][1] * 0.0625f - p1;
            acc[mi][nt][2] = acc[mi][nt][2] * 0.0625f - p0;
            acc[mi][nt][3] = acc[mi][nt][3] * 0.0625f - p1;
            rmax[2 * mi]     = fmaxf(rmax[2 * mi],     fmaxf(acc[mi][nt][0], acc[mi][nt][1]));
            rmax[2 * mi + 1] = fmaxf(rmax[2 * mi + 1], fmaxf(acc[mi][nt][2], acc[mi][nt][3]));
        }
    #pragma unroll
    for (int j = 0; j < 4; j++) {
        rmax[j] = fmaxf(rmax[j], __shfl_xor_sync(0xffffffffu, rmax[j], 1));
        rmax[j] = fmaxf(rmax[j], __shfl_xor_sync(0xffffffffu, rmax[j], 2));
    }

    __syncthreads();                        // B stage 0 dead; reuse as scratch
    float* pmax = (float*)(sm + 4096);      // [32 rows][16 warps]
    float* psum = pmax + 512;
    if ((lane & 3) == 0) {
        #pragma unroll
        for (int j = 0; j < 4; j++) pmax[(lr + j * 8) * 16 + warp] = rmax[j];
    }
    __syncthreads();
    float rm[4];
    #pragma unroll
    for (int j = 0; j < 4; j++) {
        float m = pmax[(lr + j * 8) * 16];
        #pragma unroll
        for (int w = 1; w < 16; w++) m = fmaxf(m, pmax[(lr + j * 8) * 16 + w]);
        rm[j] = m;
    }

    float rs[4] = { 0.f, 0.f, 0.f, 0.f };
    #pragma unroll
    for (int mi = 0; mi < 2; mi++)
        #pragma unroll
        for (int nt = 0; nt < 8; nt++) {
            acc[mi][nt][0] = __expf(acc[mi][nt][0] - rm[2 * mi]);
            acc[mi][nt][1] = __expf(acc[mi][nt][1] - rm[2 * mi]);
            acc[mi][nt][2] = __expf(acc[mi][nt][2] - rm[2 * mi + 1]);
            acc[mi][nt][3] = __expf(acc[mi][nt][3] - rm[2 * mi + 1]);
            rs[2 * mi]     += acc[mi][nt][0] + acc[mi][nt][1];
            rs[2 * mi + 1] += acc[mi][nt][2] + acc[mi][nt][3];
        }
    #pragma unroll
    for (int j = 0; j < 4; j++) {
        rs[j] += __shfl_xor_sync(0xffffffffu, rs[j], 1);
        rs[j] += __shfl_xor_sync(0xffffffffu, rs[j], 2);
    }
    if ((lane & 3) == 0) {
        #pragma unroll
        for (int j = 0; j < 4; j++) psum[(lr + j * 8) * 16 + warp] = rs[j];
    }
    __syncthreads();
    float inv[4];
    #pragma unroll
    for (int j = 0; j < 4; j++) {
        float s = 0.f;
        #pragma unroll
        for (int w = 0; w < 16; w++) s += psum[(lr + j * 8) * 16 + w];
        inv[j] = 1.f / s;
    }

    // ---- normalize + store ----
    #pragma unroll
    for (int mi = 0; mi < 2; mi++) {
        float* r0 = Ow + (size_t)(m0 + mi * 16 + lr) * ENUM;
        float* r1 = Ow + (size_t)(m0 + mi * 16 + lr + 8) * ENUM;
        #pragma unroll
        for (int nt = 0; nt < 8; nt++) {
            int colb = warp * 64 + nt * 8 + (lane & 3) * 2;
            *(float2*)(r0 + colb) =
                make_float2(acc[mi][nt][0] * inv[2 * mi], acc[mi][nt][1] * inv[2 * mi]);
            *(float2*)(r1 + colb) =
                make_float2(acc[mi][nt][2] * inv[2 * mi + 1], acc[mi][nt][3] * inv[2 * mi + 1]);
        }
    }
}

// ---------------------------------------------------------------------------
extern "C" void kernel_launch(void* const* d_in, const int* in_sizes, int n_in,
                              void* d_out, int out_size) {
    const float* ufeat = (const float*)d_in[0];   // [64,1024,512]
    const float* efeat = (const float*)d_in[1];   // [64,1024,256]
    const int*   neptr = (const int*)d_in[2];     // [64] int32 or int64
    const float* v     = (const float*)d_in[3];   // [256,512]
    const float* g     = (const float*)d_in[4];   // scalar
    const float* bias  = (const float*)d_in[5];   // [256]
    float* out = (float*)d_out;                   // [64,1024,1024]

    cudaFuncSetAttribute(proj_gemm, cudaFuncAttributeMaxDynamicSharedMemorySize, PSMEM_BYTES);
    cudaFuncSetAttribute(logit_softmax, cudaFuncAttributeMaxDynamicSharedMemorySize, FSMEM_BYTES);

    prep_partial<<<32, 1024>>>(v);
    conv_all<<<32896, 256>>>(ufeat, v, efeat, g, neptr);
    proj_gemm<<<dim3(2, 256), 512, PSMEM_BYTES>>>(bias);
    logit_softmax<<<dim3(UNUM / 32, BATCH), 512, FSMEM_BYTES>>>(out);
}

// round 17
// speedup vs baseline: 1.2321x; 1.0363x over previous
#include <cuda_runtime.h>
#include <cstdint>
#include <cfloat>

#define BATCH 64
#define UNUM  1024
#define ENUM  1024
#define UFD   512
#define EFD   256

__device__ float g_scale;
__device__ float g_part[32];
__device__ int   g_ne[BATCH];
__device__ uint2 g_ebf2[(size_t)BATCH * 16 * 128 * 32];  // efeat B-frags fp16 hi
__device__ uint4 g_ubf2[(size_t)4096 * 32 * 32];         // ufeat A-frags fp16 hi
__device__ uint2 g_vbf2b[(size_t)32 * 32 * 32];          // v B-frags fp16 hi
__device__ uint4 g_pbf[(size_t)4096 * 512];              // proj A-frags fp16 hi

// ---------------------------------------------------------------------------
// helpers
// ---------------------------------------------------------------------------
__device__ __forceinline__ uint32_t packh(float x0, float x1) {
    uint32_t r;   // {hi16: fp16(x1), lo16: fp16(x0)}
    asm("cvt.rn.f16x2.f32 %0, %1, %2;" : "=r"(r) : "f"(x1), "f"(x0));
    return r;
}
__device__ __forceinline__ void mma_f16(float* d, const uint32_t* a, const uint32_t* b) {
    asm volatile(
        "mma.sync.aligned.m16n8k16.row.col.f32.f16.f16.f32 "
        "{%0,%1,%2,%3}, {%4,%5,%6,%7}, {%8,%9}, {%0,%1,%2,%3};"
        : "+f"(d[0]), "+f"(d[1]), "+f"(d[2]), "+f"(d[3])
        : "r"(a[0]), "r"(a[1]), "r"(a[2]), "r"(a[3]), "r"(b[0]), "r"(b[1]));
}
__device__ __forceinline__ uint32_t smem_u32(const void* p) {
    uint32_t a;
    asm("{ .reg .u64 t; cvta.to.shared.u64 t, %1; cvt.u32.u64 %0, t; }" : "=r"(a) : "l"(p));
    return a;
}
#define CP16(dst, src) \
    asm volatile("cp.async.cg.shared.global [%0], [%1], 16;" :: "r"(dst), "l"(src) : "memory")
#define CP_COMMIT() asm volatile("cp.async.commit_group;" ::: "memory")
#define CP_WAIT1()  asm volatile("cp.async.wait_group 1;" ::: "memory")
#define CP_WAIT0()  asm volatile("cp.async.wait_group 0;" ::: "memory")

// ---------------------------------------------------------------------------
// prep_partial: ||v||^2 partials
// ---------------------------------------------------------------------------
__global__ __launch_bounds__(1024) void prep_partial(const float* __restrict__ v) {
    __shared__ float wsum[32];
    int tid = threadIdx.x, b = blockIdx.x;
    float s = 0.f;
    #pragma unroll
    for (int i = 0; i < 4; i++) {
        float x = v[b * 4096 + i * 1024 + tid];
        s += x * x;
    }
    #pragma unroll
    for (int o = 16; o; o >>= 1) s += __shfl_xor_sync(0xffffffffu, s, o);
    if ((tid & 31) == 0) wsum[tid >> 5] = s;
    __syncthreads();
    if (tid == 0) {
        float tot = 0.f;
        #pragma unroll
        for (int w = 0; w < 32; w++) tot += wsum[w];
        g_part[b] = tot;
    }
}

// ---------------------------------------------------------------------------
// vconv_full: v -> B-frags [c(32)][n8(32)][lane] (fp16 hi)
// ---------------------------------------------------------------------------
__global__ __launch_bounds__(256) void vconv_full(const float* __restrict__ v) {
    uint32_t gid = blockIdx.x * 256 + threadIdx.x;   // 32768
    int lane = gid & 31;
    int n8   = (gid >> 5) & 31;
    int c    = gid >> 10;
    int n    = n8 * 8 + (lane >> 2);
    int k0   = c * 16 + (lane & 3) * 2;
    const float* src = v + (size_t)n * UFD;
    float2 f0 = *(const float2*)(src + k0);
    float2 f1 = *(const float2*)(src + k0 + 8);
    uint2 o;
    o.x = packh(f0.x, f0.y);
    o.y = packh(f1.x, f1.y);
    g_vbf2b[(size_t)(c * 32 + n8) * 32 + lane] = o;
}

// ---------------------------------------------------------------------------
// conv_all: finalize + uconv(hi) + econv(hi), one launch.
// ---------------------------------------------------------------------------
__global__ __launch_bounds__(256) void conv_all(const float* __restrict__ uf,
                                                const float* __restrict__ ef,
                                                const float* __restrict__ g,
                                                const int* __restrict__ ne32) {
    const uint32_t b = blockIdx.x;
    const int t = threadIdx.x;
    if (b == 0 && t == 0) {
        float tot = 0.f;
        #pragma unroll
        for (int i = 0; i < 32; i++) tot += g_part[i];
        g_scale = g[0] / sqrtf(tot);
        bool is64 = true;
        for (int i = 0; i < 32; i++)
            if (ne32[2 * i + 1] != 0) { is64 = false; break; }
        for (int i = 0; i < BATCH; i++) g_ne[i] = is64 ? ne32[2 * i] : ne32[i];
    }

    if (b < 16384) {                    // ---- uconv (hi only) ----
        uint32_t gid = b * 256 + t;
        int lane = gid & 31;
        int c    = (gid >> 5) & 31;
        int m16  = gid >> 10;
        int r    = m16 * 16 + (lane >> 2);
        int k0   = c * 16 + (lane & 3) * 2;
        const float* s0 = uf + (size_t)r * UFD;
        const float* s1 = uf + (size_t)(r + 8) * UFD;
        float2 a0 = *(const float2*)(s0 + k0);
        float2 a1 = *(const float2*)(s1 + k0);
        float2 a2 = *(const float2*)(s0 + k0 + 8);
        float2 a3 = *(const float2*)(s1 + k0 + 8);
        uint4 hi;
        hi.x = packh(a0.x, a0.y); hi.y = packh(a1.x, a1.y);
        hi.z = packh(a2.x, a2.y); hi.w = packh(a3.x, a3.y);
        g_ubf2[gid] = hi;
    } else {                            // ---- econv (hi only) ----
        uint32_t gid = (b - 16384) * 256 + t;
        int lane = gid & 31;
        int n8   = (gid >> 5) & 127;
        int c    = (gid >> 12) & 15;
        int z    = gid >> 16;
        int n    = n8 * 8 + (lane >> 2);
        int k0   = c * 16 + (lane & 3) * 2;
        const float* src = ef + ((size_t)z * ENUM + n) * EFD;
        float2 f0 = *(const float2*)(src + k0);
        float2 f1 = *(const float2*)(src + k0 + 8);
        uint2 o;
        o.x = packh(f0.x, f0.y);
        o.y = packh(f1.x, f1.y);
        g_ebf2[gid] = o;
    }
}

// ---------------------------------------------------------------------------
// proj GEMM (R10-measured version): pure fp16, tile 128x128, 256 thr
// (2m x 4n warps), 3-stage cp.async, 2 CTAs/SM. -> g_pbf A-frags.
// ---------------------------------------------------------------------------
#define PSMEM_BYTES (3 * 512 * 16)   // 24 KB

__global__ __launch_bounds__(256, 2) void proj_gemm(const float* __restrict__ bias) {
    extern __shared__ uint4 su[];
    const uint32_t sbase = smem_u32(su);
    const int t = threadIdx.x;
    const int warp = t >> 5, lane = t & 31;
    const int warpM = warp >> 2, warpN = warp & 3;
    const int n0 = blockIdx.x * 128;
    const int m16base = blockIdx.y * 8;
    const int n8base = blockIdx.x * 16;

    float acc[4][4][4];
    #pragma unroll
    for (int i = 0; i < 4; i++)
        #pragma unroll
        for (int j = 0; j < 4; j++)
            #pragma unroll
            for (int r = 0; r < 4; r++) acc[i][j][r] = 0.f;

    constexpr int NCH = UFD / 16;   // 32

    auto issue = [&](int c) {
        const int s = ((unsigned)c) % 3;
        const uint32_t stb = sbase + s * 8192;
        {   // A: 256 uint4
            int m16l = t >> 5, ln = t & 31;
            const uint4* src = g_ubf2 + (size_t)((m16base + m16l) * 32 + c) * 32 + ln;
            CP16(stb + t * 16, src);
        }
        {   // B: 256 uint4
            const uint4* src = (const uint4*)(g_vbf2b + (size_t)(c * 32 + n8base) * 32) + t;
            CP16(stb + (256 + t) * 16, src);
        }
        CP_COMMIT();
    };

    issue(0);
    issue(1);
    #pragma unroll 1
    for (int c = 0; c < NCH; c++) {
        if (c == NCH - 1) CP_WAIT0(); else CP_WAIT1();
        __syncthreads();
        if (c + 2 < NCH) issue(c + 2);

        const uint4* st = su + ((unsigned)c % 3) * 512;
        const uint2* sB2 = (const uint2*)(st + 256);
        uint4 ah[4];
        uint2 bb[4];
        #pragma unroll
        for (int mt = 0; mt < 4; mt++)
            ah[mt] = st[(warpM * 4 + mt) * 32 + lane];
        #pragma unroll
        for (int nt = 0; nt < 4; nt++)
            bb[nt] = sB2[(warpN * 4 + nt) * 32 + lane];
        #pragma unroll
        for (int mt = 0; mt < 4; mt++)
            #pragma unroll
            for (int nt = 0; nt < 4; nt++)
                mma_f16(acc[mt][nt], (const uint32_t*)&ah[mt], (const uint32_t*)&bb[nt]);
    }

    const int cb0 = n0 + warpN * 32 + (lane & 3) * 2;
    const float s = g_scale;
    #pragma unroll
    for (int mt = 0; mt < 4; mt++) {
        const int m16g = m16base + warpM * 4 + mt;
        #pragma unroll
        for (int j = 0; j < 2; j++) {
            const int cglob = (n0 >> 4) + warpN * 2 + j;
            float v0[4], v1[4];
            #pragma unroll
            for (int r = 0; r < 4; r++) {
                int col = cb0 + 2 * j * 8 + (r & 1);
                v0[r] = fmaxf(fmaf(s, acc[mt][2 * j][r], bias[col]), 0.f);
                v1[r] = fmaxf(fmaf(s, acc[mt][2 * j + 1][r], bias[col + 8]), 0.f);
            }
            uint4 hi;
            hi.x = packh(v0[0], v0[1]); hi.y = packh(v0[2], v0[3]);
            hi.z = packh(v1[0], v1[1]); hi.w = packh(v1[2], v1[3]);
            g_pbf[(size_t)m16g * 512 + cglob * 32 + lane] = hi;
        }
    }
}

// ---------------------------------------------------------------------------
// Fused logit GEMM + mask + softmax — 2-CTAs/SM version.
// CTA: M=16, N=1024, 256 thr = 8 warps, warp tile 16x128 (acc[16][4]).
// A (16x256 = 512 uint4 = 8KB) plain-loaded once; B streamed 1 chunk (16 k,
// 32KB) per stage, 3 stages. smem = 104KB -> TWO CTAs co-resident per SM,
// cross-CTA overlap hides wait/barrier stalls (proj evidence: 2x256 beats
// 1x512 at 1.77x per-warp MMA rate).
// SMEM (uint4): A [0,512)   B stage s at [512 + s*2048)
// ---------------------------------------------------------------------------
#define FSMEM_BYTES ((512 + 3 * 2048) * 16)   // 106496

__global__ __launch_bounds__(256, 2) void logit_softmax(float* __restrict__ out) {
    extern __shared__ uint32_t sm[];
    const uint32_t sbase = smem_u32(sm);
    const int t = threadIdx.x;
    const int warp = t >> 5, lane = t & 31;
    const int z = blockIdx.y, m0 = blockIdx.x * 16;
    const int m16g = z * 64 + blockIdx.x;
    float* Ow = out + (size_t)z * UNUM * ENUM;

    // ---- B pipeline: 1 chunk (2048 uint4 = 32KB) per stage ----
    const uint4* ebase = (const uint4*)(g_ebf2 + (size_t)z * 16 * 4096);
    auto issueB = [&](int c) {
        const uint4* src = ebase + c * 2048;
        const uint32_t bb = sbase + (512 + ((unsigned)c % 3) * 2048) * 16;
        #pragma unroll
        for (int i = 0; i < 8; i++) {
            int f = t + i * 256;
            CP16(bb + f * 16, src + f);
        }
        CP_COMMIT();
    };
    issueB(0);
    issueB(1);

    // ---- A: plain load once (512 uint4 = 8KB) ----
    uint4* sA = (uint4*)sm;
    {
        const uint4* asrc = g_pbf + (size_t)m16g * 512;
        sA[t] = asrc[t];
        sA[256 + t] = asrc[256 + t];
    }

    float acc[16][4];
    #pragma unroll
    for (int nt = 0; nt < 16; nt++)
        #pragma unroll
        for (int r = 0; r < 4; r++) acc[nt][r] = 0.f;

    __syncthreads();   // A visible (plain ST) before chunk-0 compute

    #pragma unroll 1
    for (int c = 0; c < 16; c++) {
        if (c == 15) CP_WAIT0(); else CP_WAIT1();
        __syncthreads();
        if (c + 2 < 16) issueB(c + 2);

        const uint2* Bu = (const uint2*)(sA + 512 + ((unsigned)c % 3) * 2048);
        uint4 ah = sA[c * 32 + lane];
        #pragma unroll
        for (int nt = 0; nt < 16; nt++) {
            uint2 b = Bu[(warp * 16 + nt) * 32 + lane];
            uint32_t br[2] = { b.x, b.y };
            mma_f16(acc[nt], (const uint32_t*)&ah, br);
        }
    }

    // ---- scale + mask + per-lane row max (rows lr and lr+8) ----
    const int ne = g_ne[z];
    const int lr = lane >> 2;
    float rmax[2] = { -FLT_MAX, -FLT_MAX };
    #pragma unroll
    for (int nt = 0; nt < 16; nt++) {
        int colb = warp * 128 + nt * 8 + (lane & 3) * 2;
        float p0 = (colb >= ne) ? 1e9f : 0.f;
        float p1 = (colb + 1 >= ne) ? 1e9f : 0.f;
        acc[nt][0] = acc[nt][0] * 0.0625f - p0;
        acc[nt][1] = acc[nt][1] * 0.0625f - p1;
        acc[nt][2] = acc[nt][2] * 0.0625f - p0;
        acc[nt][3] = acc[nt][3] * 0.0625f - p1;
        rmax[0] = fmaxf(rmax[0], fmaxf(acc[nt][0], acc[nt][1]));
        rmax[1] = fmaxf(rmax[1], fmaxf(acc[nt][2], acc[nt][3]));
    }
    #pragma unroll
    for (int j = 0; j < 2; j++) {
        rmax[j] = fmaxf(rmax[j], __shfl_xor_sync(0xffffffffu, rmax[j], 1));
        rmax[j] = fmaxf(rmax[j], __shfl_xor_sync(0xffffffffu, rmax[j], 2));
    }

    __syncthreads();                        // B stages dead; reuse as scratch
    float* pmax = (float*)(sm + 2048);      // [16 rows][8 warps]
    float* psum = pmax + 128;
    if ((lane & 3) == 0) {
        pmax[lr * 8 + warp] = rmax[0];
        pmax[(lr + 8) * 8 + warp] = rmax[1];
    }
    __syncthreads();
    float rm[2];
    #pragma unroll
    for (int j = 0; j < 2; j++) {
        float m = pmax[(lr + j * 8) * 8];
        #pragma unroll
        for (int w = 1; w < 8; w++) m = fmaxf(m, pmax[(lr + j * 8) * 8 + w]);
        rm[j] = m;
    }

    float rs[2] = { 0.f, 0.f };
    #pragma unroll
    for (int nt = 0; nt < 16; nt++) {
        acc[nt][0] = __expf(acc[nt][0] - rm[0]);
        acc[nt][1] = __expf(acc[nt][1] - rm[0]);
        acc[nt][2] = __expf(acc[nt][2] - rm[1]);
        acc[nt][3] = __expf(acc[nt][3] - rm[1]);
        rs[0] += acc[nt][0] + acc[nt][1];
        rs[1] += acc[nt][2] + acc[nt][3];
    }
    #pragma unroll
    for (int j = 0; j < 2; j++) {
        rs[j] += __shfl_xor_sync(0xffffffffu, rs[j], 1);
        rs[j] += __shfl_xor_sync(0xffffffffu, rs[j], 2);
    }
    if ((lane & 3) == 0) {
        psum[lr * 8 + warp] = rs[0];
        psum[(lr + 8) * 8 + warp] = rs[1];
    }
    __syncthreads();
    float inv[2];
    #pragma unroll
    for (int j = 0; j < 2; j++) {
        float s = 0.f;
        #pragma unroll
        for (int w = 0; w < 8; w++) s += psum[(lr + j * 8) * 8 + w];
        inv[j] = 1.f / s;
    }

    // ---- normalize + store ----
    float* r0 = Ow + (size_t)(m0 + lr) * ENUM;
    float* r1 = Ow + (size_t)(m0 + lr + 8) * ENUM;
    #pragma unroll
    for (int nt = 0; nt < 16; nt++) {
        int colb = warp * 128 + nt * 8 + (lane & 3) * 2;
        *(float2*)(r0 + colb) = make_float2(acc[nt][0] * inv[0], acc[nt][1] * inv[0]);
        *(float2*)(r1 + colb) = make_float2(acc[nt][2] * inv[1], acc[nt][3] * inv[1]);
    }
}

// ---------------------------------------------------------------------------
extern "C" void kernel_launch(void* const* d_in, const int* in_sizes, int n_in,
                              void* d_out, int out_size) {
    const float* ufeat = (const float*)d_in[0];   // [64,1024,512]
    const float* efeat = (const float*)d_in[1];   // [64,1024,256]
    const int*   neptr = (const int*)d_in[2];     // [64] int32 or int64
    const float* v     = (const float*)d_in[3];   // [256,512]
    const float* g     = (const float*)d_in[4];   // scalar
    const float* bias  = (const float*)d_in[5];   // [256]
    float* out = (float*)d_out;                   // [64,1024,1024]

    cudaFuncSetAttribute(proj_gemm, cudaFuncAttributeMaxDynamicSharedMemorySize, PSMEM_BYTES);
    cudaFuncSetAttribute(logit_softmax, cudaFuncAttributeMaxDynamicSharedMemorySize, FSMEM_BYTES);

    prep_partial<<<32, 1024>>>(v);
    vconv_full<<<128, 256>>>(v);
    conv_all<<<32768, 256>>>(ufeat, efeat, g, neptr);
    proj_gemm<<<dim3(2, 512), 256, PSMEM_BYTES>>>(bias);
    logit_softmax<<<dim3(UNUM / 16, BATCH), 256, FSMEM_BYTES>>>(out);
}